// round 10
// baseline (speedup 1.0000x reference)
#include <cuda_runtime.h>
#include <math.h>

#define BB 4
#define TT 2048
#define DD 1024
#define HH 16
#define HDIM 64
#define MM (BB*TT)   /* 8192 */
#define LOW_W 64
#define LOW_A 64
#define LOW_G 160
#define DECAY_SCALE (-0.6065306597126334f)
#define GN_EPS (64.0f*1e-5f)

// ---------------- scratch (device globals: allocation is banned) ----------
__device__ float g_r [MM*DD];
__device__ float g_w [MM*DD];   // exp(w) after the w down-GEMM (ACT=4)
__device__ float g_k [MM*DD];
__device__ float g_v [MM*DD];
__device__ float g_a [MM*DD];
__device__ float g_g [MM*DD];
__device__ float g_kk[MM*DD];   // -kk after prep
__device__ float g_b [MM*DD];   // kk*a after prep
__device__ float g_o [MM*DD];
__device__ float g_y [MM*DD];
__device__ float g_uw[MM*LOW_W];
__device__ float g_ua[MM*LOW_A];
__device__ float g_ug[MM*LOW_G];

// ---------------- helpers -------------------------------------------------
__device__ __forceinline__ float f2tf32(float x) {
    unsigned u;
    asm("cvt.rna.tf32.f32 %0, %1;" : "=r"(u) : "f"(x));
    return __uint_as_float(u);
}

__device__ __forceinline__ void mma_tf32(float* c, const unsigned* a, const unsigned* b) {
    asm volatile(
        "mma.sync.aligned.m16n8k8.row.col.f32.tf32.tf32.f32 "
        "{%0,%1,%2,%3}, {%4,%5,%6,%7}, {%8,%9}, {%0,%1,%2,%3};\n"
        : "+f"(c[0]), "+f"(c[1]), "+f"(c[2]), "+f"(c[3])
        : "r"(a[0]), "r"(a[1]), "r"(a[2]), "r"(a[3]), "r"(b[0]), "r"(b[1]));
}

__device__ __forceinline__ float apply_act(float v, int ACT) {
    if (ACT == 1) return tanhf(v);
    if (ACT == 2) return 1.f / (1.f + expf(-v));
    if (ACT == 3) return DECAY_SCALE * (1.f / (1.f + expf(-v)));
    if (ACT == 4) return expf(DECAY_SCALE * (1.f / (1.f + expf(-v))));
    return v;
}

// ---------------- tf32 tensor-core GEMM, packed-fragment smem -------------
// C[M x N] = act( A'[M x K] @ B[K x N] + bias ), A' = token-shift-mixed A when
// mix != null (requires K == DD).  BM=128, BK=16, 256 threads.
// A smem layout: [ks][rb][g][tg][quad], rb stride ARB=140 (== 12 mod 32) and a
// bit-shuffled loader row map -> A STS is 2-way (was 4-way); fragment read is
// one LDS.128, conflict-free.  B smem: [ks][c][tg][pair] -> fragment LDS.64.
template<int BN_, int WARPS_M, int WARPS_N, int ACT>
__global__ __launch_bounds__(256, 2)
void gemm_tf32(const float* __restrict__ A, const float* __restrict__ B,
               float* __restrict__ C, int N, int K,
               const float* __restrict__ bias, const float* __restrict__ mix)
{
    constexpr int BM = 128, BK = 16;
    constexpr int WMT = BM / WARPS_M;
    constexpr int WNT = BN_ / WARPS_N;
    constexpr int MF = WMT / 16, NF = WNT / 8;
    constexpr int ARB = 140;             // rb stride: 140 mod 32 = 12 (bank spread)
    constexpr int AKS = 8 * ARB;         // 1120 words per ks slice
    constexpr int ASZ = 2 * AKS;         // per buffer
    constexpr int BKS = BN_ * 8;
    constexpr int BSZ = 2 * BKS;
    constexpr int BQ    = BN_ / 4;
    constexpr int RLOAD = 256 / BQ;
    constexpr int PASS  = 16 / RLOAD;

    __shared__ alignas(16) float As[2][ASZ];
    __shared__ alignas(16) float Bs[2][BSZ];

    int tid  = threadIdx.x;
    int lane = tid & 31, warp = tid >> 5;
    int g  = lane >> 2, tg = lane & 3;
    int wm = (warp % WARPS_M) * WMT;
    int wn = (warp / WARPS_M) * WNT;
    int rb0 = wm >> 4;

    int rowBase = blockIdx.y * BM;
    int colBase = blockIdx.x * BN_;

    // A loader: bit-shuffled row map so each warp spans rb 0..3, gg-parity, hi
    // -> 16 distinct STS banks (2-way) instead of 8 (4-way).
    int t6 = tid & 63;
    int ll = t6 & 31, wbit = t6 >> 5;
    int arow = ((ll >> 2) & 3) * 16 + ((ll >> 1) & 1) * 8
             + ((ll & 1) + 2 * ((ll >> 4) & 1) + 4 * wbit);
    int ac4 = tid >> 6;
    int a_ks = ac4 >> 1, a_half = ac4 & 1;
    int bkr  = tid % RLOAD, bc4 = tid / RLOAD;

    float acc[MF][NF][4];
#pragma unroll
    for (int i = 0; i < MF; i++)
#pragma unroll
        for (int j = 0; j < NF; j++)
#pragma unroll
            for (int q = 0; q < 4; q++) acc[i][j][q] = 0.f;

    float4 ra[2], rbv[PASS];
    const int kTiles = K / BK;

#define LOAD_TILE(KT) { \
    float4 mmix = make_float4(0.f, 0.f, 0.f, 0.f); \
    if (mix) mmix = *(const float4*)(mix + (KT) * BK + ac4 * 4); \
    _Pragma("unroll") \
    for (int p = 0; p < 2; p++) { \
        int m = rowBase + arow + p * 64; \
        const float* ap = A + (size_t)m * K + (KT) * BK + ac4 * 4; \
        float4 v = *(const float4*)ap; \
        if (mix) { \
            int tt = m & (TT - 1); \
            float4 pv = tt ? *(const float4*)(ap - K) : make_float4(0.f,0.f,0.f,0.f); \
            v.x += (pv.x - v.x) * mmix.x; v.y += (pv.y - v.y) * mmix.y; \
            v.z += (pv.z - v.z) * mmix.z; v.w += (pv.w - v.w) * mmix.w; \
        } \
        ra[p] = v; \
    } \
    _Pragma("unroll") \
    for (int p = 0; p < PASS; p++) { \
        int kr = bkr + p * RLOAD; \
        int cc = colBase + bc4 * 4; \
        rbv[p] = (cc < N) ? *(const float4*)(B + (size_t)((KT) * BK + kr) * N + cc) \
                          : make_float4(0.f, 0.f, 0.f, 0.f); \
    } }

#define STORE_TILE(BUF) { \
    _Pragma("unroll") \
    for (int p = 0; p < 2; p++) { \
        int r = arow + 64 * p; \
        int rb = r >> 4, gg = r & 7, hi = (r >> 3) & 1; \
        float* d = &As[BUF][a_ks * AKS + rb * ARB + gg * 16 + hi + 2 * a_half]; \
        d[0]  = f2tf32(ra[p].x); d[4]  = f2tf32(ra[p].y); \
        d[8]  = f2tf32(ra[p].z); d[12] = f2tf32(ra[p].w); \
    } \
    _Pragma("unroll") \
    for (int p = 0; p < PASS; p++) { \
        int kr = bkr + p * RLOAD; \
        int ks = kr >> 3, kl = kr & 7, btg = kl & 3, hs = kl >> 2; \
        float* d = &Bs[BUF][ks * BKS + (bc4 * 4) * 8 + btg * 2 + hs]; \
        d[0]  = f2tf32(rbv[p].x); d[8]  = f2tf32(rbv[p].y); \
        d[16] = f2tf32(rbv[p].z); d[24] = f2tf32(rbv[p].w); \
    } }

    LOAD_TILE(0);
    STORE_TILE(0);
    __syncthreads();

    int cur = 0;
    for (int kt = 1; kt <= kTiles; kt++) {
        if (kt < kTiles) LOAD_TILE(kt);

#pragma unroll
        for (int ks = 0; ks < 2; ks++) {
            unsigned af[MF][4], bf[NF][2];
#pragma unroll
            for (int i = 0; i < MF; i++) {
                float4 v = *(const float4*)&As[cur][ks * AKS + (rb0 + i) * ARB + g * 16 + tg * 4];
                af[i][0] = __float_as_uint(v.x); af[i][1] = __float_as_uint(v.y);
                af[i][2] = __float_as_uint(v.z); af[i][3] = __float_as_uint(v.w);
            }
#pragma unroll
            for (int j = 0; j < NF; j++) {
                float2 v = *(const float2*)&Bs[cur][ks * BKS + (wn + j * 8 + g) * 8 + tg * 2];
                bf[j][0] = __float_as_uint(v.x); bf[j][1] = __float_as_uint(v.y);
            }
#pragma unroll
            for (int i = 0; i < MF; i++)
#pragma unroll
                for (int j = 0; j < NF; j++)
                    mma_tf32(acc[i][j], af[i], bf[j]);
        }

        if (kt < kTiles) {
            int nxt = cur ^ 1;
            STORE_TILE(nxt);
        }
        __syncthreads();
        cur ^= 1;
    }
#undef LOAD_TILE
#undef STORE_TILE

#pragma unroll
    for (int i = 0; i < MF; i++) {
#pragma unroll
        for (int j = 0; j < NF; j++) {
            int r0 = rowBase + wm + i * 16 + g;
            int c0 = colBase + wn + j * 8 + 2 * tg;
#pragma unroll
            for (int q = 0; q < 4; q++) {
                int rr = r0 + (q >> 1) * 8;
                int cc = c0 + (q & 1);
                if (cc < N) {
                    float v = acc[i][j][q];
                    if (bias) v += bias[cc];
                    v = apply_act(v, ACT);
                    C[(size_t)rr * N + cc] = v;
                }
            }
        }
    }
}

// ---------------- prep: kk = l2norm(k*k_k); b = kk*a; nk = -kk; k rescale --
__global__ void prep_kernel(const float* __restrict__ k_k,
                            const float* __restrict__ k_a)
{
    int hidx = blockIdx.x;             // MM*HH
    int m = hidx >> 4, h = hidx & 15;
    int lane = threadIdx.x;            // 32
    size_t base = (size_t)m * DD + h * HDIM;
    int d0 = h * HDIM + lane, d1 = d0 + 32;

    float k0 = g_k[base + lane], k1 = g_k[base + lane + 32];
    float q0 = k0 * k_k[d0],     q1 = k1 * k_k[d1];
    float ss = q0 * q0 + q1 * q1;
#pragma unroll
    for (int o = 16; o > 0; o >>= 1) ss += __shfl_xor_sync(0xffffffffu, ss, o);
    float inv = 1.f / fmaxf(sqrtf(ss), 1e-12f);
    float kk0 = q0 * inv, kk1 = q1 * inv;

    float a0 = g_a[base + lane], a1 = g_a[base + lane + 32];
    g_kk[base + lane]      = -kk0;
    g_kk[base + lane + 32] = -kk1;
    g_b[base + lane]       = kk0 * a0;
    g_b[base + lane + 32]  = kk1 * a1;
    g_k[base + lane]       = k0 * (1.f + (a0 - 1.f) * k_a[d0]);
    g_k[base + lane + 32]  = k1 * (1.f + (a1 - 1.f) * k_a[d1]);
}

// ---------------- sequential delta-rule scan (round-8 proven version) ------
// 16 row-groups of 4 rows -> 1024 independent one-warp blocks; warps slip
// freely (no cross-warp barriers) which hides the serial per-step latency.
// 4-deep register prefetch, manually unrolled x4 (compile-time slot indices).
#define GROUPS 16
#define ROWS   4
__global__ void scan_kernel()
{
    int idx = blockIdx.x;
    int g  = idx & (GROUPS - 1);
    int bh = idx >> 4;
    int b = bh >> 4, h = bh & 15;
    int tid = threadIdx.x;
    int row = tid >> 3;       // 0..3
    int c   = tid & 7;        // 0..7
    int c0  = c * 8;
    int j2  = tid * 2;

    __shared__ alignas(16) float sw[64], sr[64], sk[64], sb[64], snk[64], sv[ROWS];
    float S[8];
#pragma unroll
    for (int j = 0; j < 8; j++) S[j] = 0.f;

    size_t basebh = ((size_t)b * TT) * DD + h * HDIM;

    float2 Pw[4], Pr[4], Pk[4], Pb[4], Pn[4];
    float  Pv[4];
#pragma unroll
    for (int q = 0; q < 4; q++) {          // fully unrolled: static indices
        size_t pb = basebh + (size_t)q * DD;
        Pw[q] = *(const float2*)(g_w + pb + j2);
        Pr[q] = *(const float2*)(g_r + pb + j2);
        Pk[q] = *(const float2*)(g_k + pb + j2);
        Pb[q] = *(const float2*)(g_b + pb + j2);
        Pn[q] = *(const float2*)(g_kk + pb + j2);
        Pv[q] = (tid < ROWS) ? g_v[pb + g * ROWS + tid] : 0.f;
    }

    for (int t = 0; t < TT; t += 4) {
#pragma unroll
        for (int q = 0; q < 4; q++) {      // unrolled: Pw[q] etc. stay in regs
            int tq = t + q;
            *(float2*)&sw[j2]  = Pw[q];
            *(float2*)&sr[j2]  = Pr[q];
            *(float2*)&sk[j2]  = Pk[q];
            *(float2*)&sb[j2]  = Pb[q];
            *(float2*)&snk[j2] = Pn[q];
            if (tid < ROWS) sv[tid] = Pv[q];
            __syncwarp();

            if (tq + 4 < TT) {
                size_t pb = basebh + (size_t)(tq + 4) * DD;
                Pw[q] = *(const float2*)(g_w + pb + j2);
                Pr[q] = *(const float2*)(g_r + pb + j2);
                Pk[q] = *(const float2*)(g_k + pb + j2);
                Pb[q] = *(const float2*)(g_b + pb + j2);
                Pn[q] = *(const float2*)(g_kk + pb + j2);
                if (tid < ROWS) Pv[q] = g_v[pb + g * ROWS + tid];
            }

            float pa0 = 0.f, pa1 = 0.f;
#pragma unroll
            for (int j = 0; j < 4; j++)  pa0 = fmaf(S[j],     snk[c0 + j],     pa0);
#pragma unroll
            for (int j = 0; j < 4; j++)  pa1 = fmaf(S[j + 4], snk[c0 + j + 4], pa1);
            float pa = pa0 + pa1;
            pa += __shfl_xor_sync(0xffffffffu, pa, 1);
            pa += __shfl_xor_sync(0xffffffffu, pa, 2);
            pa += __shfl_xor_sync(0xffffffffu, pa, 4);

            float vr = sv[row];
            float po0 = 0.f, po1 = 0.f;
#pragma unroll
            for (int j = 0; j < 8; j++) {
                int kc = c0 + j;
                float ssv = fmaf(S[j], sw[kc], fmaf(pa, sb[kc], vr * sk[kc]));
                S[j] = ssv;
                if (j < 4) po0 = fmaf(ssv, sr[kc], po0);
                else       po1 = fmaf(ssv, sr[kc], po1);
            }
            float po = po0 + po1;
            po += __shfl_xor_sync(0xffffffffu, po, 1);
            po += __shfl_xor_sync(0xffffffffu, po, 2);
            po += __shfl_xor_sync(0xffffffffu, po, 4);
            if (c == 0) g_o[basebh + (size_t)tq * DD + g * ROWS + row] = po;
            __syncwarp();
        }
    }
}

// ---------------- post: GroupNorm(head) + corr + gate ---------------------
__global__ void post_kernel(const float* __restrict__ r_k,
                            const float* __restrict__ gnw,
                            const float* __restrict__ gnb)
{
    int hidx = blockIdx.x;
    int m = hidx >> 4, h = hidx & 15;
    int lane = threadIdx.x;
    size_t base = (size_t)m * DD + h * HDIM;
    int d0 = h * HDIM + lane, d1 = d0 + 32;

    float o0 = g_o[base + lane], o1 = g_o[base + lane + 32];
    float s = o0 + o1;
#pragma unroll
    for (int o = 16; o > 0; o >>= 1) s += __shfl_xor_sync(0xffffffffu, s, o);
    float mu = s * (1.f / 64.f);
    float e0 = o0 - mu, e1 = o1 - mu;
    float vs = e0 * e0 + e1 * e1;
#pragma unroll
    for (int o = 16; o > 0; o >>= 1) vs += __shfl_xor_sync(0xffffffffu, vs, o);
    float inv = rsqrtf(vs * (1.f / 64.f) + GN_EPS);

    float on0 = e0 * inv * gnw[d0] + gnb[d0];
    float on1 = e1 * inv * gnw[d1] + gnb[d1];

    float dot = g_r[base + lane]      * g_k[base + lane]      * r_k[d0]
              + g_r[base + lane + 32] * g_k[base + lane + 32] * r_k[d1];
#pragma unroll
    for (int o = 16; o > 0; o >>= 1) dot += __shfl_xor_sync(0xffffffffu, dot, o);

    g_y[base + lane]      = (on0 + dot * g_v[base + lane])      * g_g[base + lane];
    g_y[base + lane + 32] = (on1 + dot * g_v[base + lane + 32]) * g_g[base + lane + 32];
}

// ---------------------------------------------------------------------------
extern "C" void kernel_launch(void* const* d_in, const int* in_sizes, int n_in,
                              void* d_out, int out_size)
{
    const float* x     = (const float*)d_in[0];
    const float* mix_r = (const float*)d_in[1];
    const float* mix_w = (const float*)d_in[2];
    const float* mix_k = (const float*)d_in[3];
    const float* mix_v = (const float*)d_in[4];
    const float* mix_a = (const float*)d_in[5];
    const float* mix_g = (const float*)d_in[6];
    const float* k_k   = (const float*)d_in[7];
    const float* k_a   = (const float*)d_in[8];
    const float* r_k   = (const float*)d_in[9];
    const float* Wr    = (const float*)d_in[10];
    const float* Wk    = (const float*)d_in[11];
    const float* Wv    = (const float*)d_in[12];
    const float* Wo    = (const float*)d_in[13];
    const float* wA    = (const float*)d_in[14];
    const float* wB    = (const float*)d_in[15];
    const float* w_bias= (const float*)d_in[16];
    const float* aA    = (const float*)d_in[17];
    const float* aB    = (const float*)d_in[18];
    const float* a_bias= (const float*)d_in[19];
    const float* gA    = (const float*)d_in[20];
    const float* gB    = (const float*)d_in[21];
    const float* gnw   = (const float*)d_in[22];
    const float* gnb   = (const float*)d_in[23];
    float* out = (float*)d_out;

    float *pr, *pw, *pk, *pv, *pa, *pg, *py, *puw, *pua, *pug;
    cudaGetSymbolAddress((void**)&pr,  g_r);
    cudaGetSymbolAddress((void**)&pw,  g_w);
    cudaGetSymbolAddress((void**)&pk,  g_k);
    cudaGetSymbolAddress((void**)&pv,  g_v);
    cudaGetSymbolAddress((void**)&pa,  g_a);
    cudaGetSymbolAddress((void**)&pg,  g_g);
    cudaGetSymbolAddress((void**)&py,  g_y);
    cudaGetSymbolAddress((void**)&puw, g_uw);
    cudaGetSymbolAddress((void**)&pua, g_ua);
    cudaGetSymbolAddress((void**)&pug, g_ug);

    dim3 blk(256);
    dim3 grdBig(DD / 128, MM / 128);            // (8, 64) : N=1024
    dim3 grdUp64(1, MM / 128);                  // (1, 64) : N=64
    dim3 grdUp160((LOW_G + 63) / 64, MM / 128); // (3, 64) : N=160

    // 1. big projections with fused token-shift mix (tf32 tensor cores)
    gemm_tf32<128,2,4,0><<<grdBig, blk>>>(x, Wr, pr, DD, DD, nullptr, mix_r);
    gemm_tf32<128,2,4,0><<<grdBig, blk>>>(x, Wk, pk, DD, DD, nullptr, mix_k);
    gemm_tf32<128,2,4,0><<<grdBig, blk>>>(x, Wv, pv, DD, DD, nullptr, mix_v);

    // 2. w lora: tanh(mix(x)@wA) @ wB + bias -> exp(DECAY_SCALE*sigmoid) fused
    gemm_tf32<64,4,2,1><<<grdUp64, blk>>>(x, wA, puw, LOW_W, DD, nullptr, mix_w);
    gemm_tf32<128,2,4,4><<<grdBig, blk>>>(puw, wB, pw, DD, LOW_W, w_bias, nullptr);

    // 3. a lora: (mix(x)@aA) @ aB + bias -> sigmoid
    gemm_tf32<64,4,2,0><<<grdUp64, blk>>>(x, aA, pua, LOW_A, DD, nullptr, mix_a);
    gemm_tf32<128,2,4,2><<<grdBig, blk>>>(pua, aB, pa, DD, LOW_A, a_bias, nullptr);

    // 4. g lora: sigmoid(mix(x)@gA) @ gB
    gemm_tf32<64,4,2,2><<<grdUp160, blk>>>(x, gA, pug, LOW_G, DD, nullptr, mix_g);
    gemm_tf32<128,2,4,0><<<grdBig, blk>>>(pug, gB, pg, DD, LOW_G, nullptr, nullptr);

    // 5. kk normalize + b/nk precompute + k rescale
    prep_kernel<<<MM * HH, 32>>>(k_k, k_a);

    // 6. sequential generalized delta-rule scan (round-8 independent warps)
    scan_kernel<<<BB * HH * GROUPS, 32>>>();

    // 7. GroupNorm + correction + gate
    post_kernel<<<MM * HH, 32>>>(r_k, gnw, gnb);

    // 8. output projection
    gemm_tf32<128,2,4,0><<<grdBig, blk>>>(py, Wo, out, DD, DD, nullptr, nullptr);
}

// round 11
// speedup vs baseline: 1.1267x; 1.1267x over previous
#include <cuda_runtime.h>
#include <math.h>

#define BB 4
#define TT 2048
#define DD 1024
#define HH 16
#define HDIM 64
#define MM (BB*TT)   /* 8192 */
#define LOW_W 64
#define LOW_A 64
#define LOW_G 160
#define DECAY_SCALE (-0.6065306597126334f)
#define GN_EPS (64.0f*1e-5f)

// ---------------- scratch (device globals: allocation is banned) ----------
__device__ float g_xr[MM*DD];
__device__ float g_xw[MM*DD];
__device__ float g_xk[MM*DD];
__device__ float g_xv[MM*DD];
__device__ float g_xa[MM*DD];
__device__ float g_xg[MM*DD];
__device__ float g_r [MM*DD];
__device__ float g_w [MM*DD];   // holds exp(w) after the w GEMM (ACT=4)
__device__ float g_k [MM*DD];
__device__ float g_v [MM*DD];
__device__ float g_a [MM*DD];
__device__ float g_g [MM*DD];
__device__ float g_kk[MM*DD];   // holds -kk (normalized) after prep
__device__ float g_b [MM*DD];   // holds kk*a after prep
__device__ float g_o [MM*DD];
__device__ float g_y [MM*DD];
__device__ float g_uw[MM*LOW_W];
__device__ float g_ua[MM*LOW_A];
__device__ float g_ug[MM*LOW_G];

// ---------------- helpers -------------------------------------------------
__device__ __forceinline__ float f2tf32(float x) {
    unsigned u;
    asm("cvt.rna.tf32.f32 %0, %1;" : "=r"(u) : "f"(x));
    return __uint_as_float(u);
}

__device__ __forceinline__ void mma_tf32(float* c, const unsigned* a, const unsigned* b) {
    asm volatile(
        "mma.sync.aligned.m16n8k8.row.col.f32.tf32.tf32.f32 "
        "{%0,%1,%2,%3}, {%4,%5,%6,%7}, {%8,%9}, {%0,%1,%2,%3};\n"
        : "+f"(c[0]), "+f"(c[1]), "+f"(c[2]), "+f"(c[3])
        : "r"(a[0]), "r"(a[1]), "r"(a[2]), "r"(a[3]), "r"(b[0]), "r"(b[1]));
}

__device__ __forceinline__ float apply_act(float v, int ACT) {
    if (ACT == 1) return tanhf(v);
    if (ACT == 2) return 1.f / (1.f + expf(-v));
    if (ACT == 3) return DECAY_SCALE * (1.f / (1.f + expf(-v)));
    if (ACT == 4) return expf(DECAY_SCALE * (1.f / (1.f + expf(-v))));
    return v;
}

// ---------------- mix pre-pass: build the 6 token-shifted inputs ----------
__global__ void mix_kernel(const float* __restrict__ x,
                           const float* __restrict__ m_r, const float* __restrict__ m_w,
                           const float* __restrict__ m_k, const float* __restrict__ m_v,
                           const float* __restrict__ m_a, const float* __restrict__ m_g)
{
    int i = blockIdx.x * blockDim.x + threadIdx.x;   // float4 index
    if (i >= MM * DD / 4) return;
    int c4 = i & (DD / 4 - 1);
    int m  = i >> 8;                                  // token row (D/4 = 256)
    int t  = m & (TT - 1);
    const float4* x4 = (const float4*)x;
    float4 xv = x4[i];
    float4 pv = t ? x4[i - DD / 4] : make_float4(0.f, 0.f, 0.f, 0.f);
    float4 d  = make_float4(pv.x - xv.x, pv.y - xv.y, pv.z - xv.z, pv.w - xv.w);

#define APPLY(MIX, OUT) { \
    float4 mm = ((const float4*)MIX)[c4]; \
    float4 o; \
    o.x = xv.x + d.x * mm.x; o.y = xv.y + d.y * mm.y; \
    o.z = xv.z + d.z * mm.z; o.w = xv.w + d.w * mm.w; \
    ((float4*)OUT)[i] = o; }
    APPLY(m_r, g_xr); APPLY(m_w, g_xw); APPLY(m_k, g_xk);
    APPLY(m_v, g_xv); APPLY(m_a, g_xa); APPLY(m_g, g_xg);
#undef APPLY
}

// ---------------- tf32 tensor-core GEMM, packed-fragment smem -------------
// C[M x N] = act( A[M x K] @ B[K x N] + bias ).  BM=128, BK=16, 256 threads.
// A smem: [ks][rb][g][tg][quad], rb stride ARB=140 (== 12 mod 32) + a
// bit-shuffled loader row map -> A STS is 2-way banked (was 4-way).
// Fragment reads unchanged: A = one LDS.128, B = one LDS.64, conflict-free.
template<int BN_, int WARPS_M, int WARPS_N, int ACT>
__global__ __launch_bounds__(256)
void gemm_tf32(const float* __restrict__ A, const float* __restrict__ B,
               float* __restrict__ C, int N, int K,
               const float* __restrict__ bias)
{
    constexpr int BM = 128, BK = 16;
    constexpr int WMT = BM / WARPS_M;
    constexpr int WNT = BN_ / WARPS_N;
    constexpr int MF = WMT / 16, NF = WNT / 8;
    constexpr int ARB = 140;             // rb stride: 140 mod 32 = 12 (bank spread)
    constexpr int AKS = 8 * ARB;         // 1120 words per ks slice
    constexpr int ASZ = 2 * AKS;
    constexpr int BKS = BN_ * 8;
    constexpr int BSZ = 2 * BKS;
    constexpr int BQ    = BN_ / 4;
    constexpr int RLOAD = 256 / BQ;
    constexpr int PASS  = 16 / RLOAD;

    __shared__ alignas(16) float As[2][ASZ];
    __shared__ alignas(16) float Bs[2][BSZ];

    int tid  = threadIdx.x;
    int lane = tid & 31, warp = tid >> 5;
    int g  = lane >> 2, tg = lane & 3;
    int wm = (warp % WARPS_M) * WMT;
    int wn = (warp / WARPS_M) * WNT;
    int rb0 = wm >> 4;

    int rowBase = blockIdx.y * BM;
    int colBase = blockIdx.x * BN_;

    // A loader: bit-shuffled row map so each warp's stores span rb 0..3,
    // gg-parity, hi -> 16 distinct banks (2-way) instead of 8 (4-way).
    int t6 = tid & 63;
    int ll = t6 & 31, wbit = t6 >> 5;
    int arow = ((ll >> 2) & 3) * 16 + ((ll >> 1) & 1) * 8
             + ((ll & 1) + 2 * ((ll >> 4) & 1) + 4 * wbit);
    int ac4 = tid >> 6;
    int a_ks = ac4 >> 1, a_half = ac4 & 1;
    int bkr  = tid % RLOAD, bc4 = tid / RLOAD;

    float acc[MF][NF][4];
#pragma unroll
    for (int i = 0; i < MF; i++)
#pragma unroll
        for (int j = 0; j < NF; j++)
#pragma unroll
            for (int q = 0; q < 4; q++) acc[i][j][q] = 0.f;

    float4 ra[2], rbv[PASS];
    const int kTiles = K / BK;

#define LOAD_TILE(KT) { \
    _Pragma("unroll") \
    for (int p = 0; p < 2; p++) { \
        int r = rowBase + arow + p * 64; \
        ra[p] = *(const float4*)(A + (size_t)r * K + (KT) * BK + ac4 * 4); \
    } \
    _Pragma("unroll") \
    for (int p = 0; p < PASS; p++) { \
        int kr = bkr + p * RLOAD; \
        int cc = colBase + bc4 * 4; \
        rbv[p] = (cc < N) ? *(const float4*)(B + (size_t)((KT) * BK + kr) * N + cc) \
                          : make_float4(0.f, 0.f, 0.f, 0.f); \
    } }

#define STORE_TILE(BUF) { \
    _Pragma("unroll") \
    for (int p = 0; p < 2; p++) { \
        int r = arow + 64 * p; \
        int rb = r >> 4, gg = r & 7, hi = (r >> 3) & 1; \
        float* d = &As[BUF][a_ks * AKS + rb * ARB + gg * 16 + hi + 2 * a_half]; \
        d[0]  = f2tf32(ra[p].x); d[4]  = f2tf32(ra[p].y); \
        d[8]  = f2tf32(ra[p].z); d[12] = f2tf32(ra[p].w); \
    } \
    _Pragma("unroll") \
    for (int p = 0; p < PASS; p++) { \
        int kr = bkr + p * RLOAD; \
        int ks = kr >> 3, kl = kr & 7, btg = kl & 3, hs = kl >> 2; \
        float* d = &Bs[BUF][ks * BKS + (bc4 * 4) * 8 + btg * 2 + hs]; \
        d[0]  = f2tf32(rbv[p].x); d[8]  = f2tf32(rbv[p].y); \
        d[16] = f2tf32(rbv[p].z); d[24] = f2tf32(rbv[p].w); \
    } }

    LOAD_TILE(0);
    STORE_TILE(0);
    __syncthreads();

    int cur = 0;
    for (int kt = 1; kt <= kTiles; kt++) {
        if (kt < kTiles) LOAD_TILE(kt);

#pragma unroll
        for (int ks = 0; ks < 2; ks++) {
            unsigned af[MF][4], bf[NF][2];
#pragma unroll
            for (int i = 0; i < MF; i++) {
                float4 v = *(const float4*)&As[cur][ks * AKS + (rb0 + i) * ARB + g * 16 + tg * 4];
                af[i][0] = __float_as_uint(v.x); af[i][1] = __float_as_uint(v.y);
                af[i][2] = __float_as_uint(v.z); af[i][3] = __float_as_uint(v.w);
            }
#pragma unroll
            for (int j = 0; j < NF; j++) {
                float2 v = *(const float2*)&Bs[cur][ks * BKS + (wn + j * 8 + g) * 8 + tg * 2];
                bf[j][0] = __float_as_uint(v.x); bf[j][1] = __float_as_uint(v.y);
            }
#pragma unroll
            for (int i = 0; i < MF; i++)
#pragma unroll
                for (int j = 0; j < NF; j++)
                    mma_tf32(acc[i][j], af[i], bf[j]);
        }

        if (kt < kTiles) {
            int nxt = cur ^ 1;
            STORE_TILE(nxt);
        }
        __syncthreads();
        cur ^= 1;
    }
#undef LOAD_TILE
#undef STORE_TILE

#pragma unroll
    for (int i = 0; i < MF; i++) {
#pragma unroll
        for (int j = 0; j < NF; j++) {
            int r0 = rowBase + wm + i * 16 + g;
            int c0 = colBase + wn + j * 8 + 2 * tg;
#pragma unroll
            for (int q = 0; q < 4; q++) {
                int rr = r0 + (q >> 1) * 8;
                int cc = c0 + (q & 1);
                if (cc < N) {
                    float v = acc[i][j][q];
                    if (bias) v += bias[cc];
                    v = apply_act(v, ACT);
                    C[(size_t)rr * N + cc] = v;
                }
            }
        }
    }
}

// ---------------- prep: kk = l2norm(k*k_k); b = kk*a; nk = -kk; k rescale --
__global__ void prep_kernel(const float* __restrict__ k_k,
                            const float* __restrict__ k_a)
{
    int hidx = blockIdx.x;             // MM*HH
    int m = hidx >> 4, h = hidx & 15;
    int lane = threadIdx.x;            // 32
    size_t base = (size_t)m * DD + h * HDIM;
    int d0 = h * HDIM + lane, d1 = d0 + 32;

    float k0 = g_k[base + lane], k1 = g_k[base + lane + 32];
    float q0 = k0 * k_k[d0],     q1 = k1 * k_k[d1];
    float ss = q0 * q0 + q1 * q1;
#pragma unroll
    for (int o = 16; o > 0; o >>= 1) ss += __shfl_xor_sync(0xffffffffu, ss, o);
    float inv = 1.f / fmaxf(sqrtf(ss), 1e-12f);
    float kk0 = q0 * inv, kk1 = q1 * inv;

    float a0 = g_a[base + lane], a1 = g_a[base + lane + 32];
    g_kk[base + lane]      = -kk0;
    g_kk[base + lane + 32] = -kk1;
    g_b[base + lane]       = kk0 * a0;
    g_b[base + lane + 32]  = kk1 * a1;
    g_k[base + lane]       = k0 * (1.f + (a0 - 1.f) * k_a[d0]);
    g_k[base + lane + 32]  = k1 * (1.f + (a1 - 1.f) * k_a[d1]);
}

// ---------------- sequential delta-rule scan (round-8 proven version) ------
// 16 row-groups of 4 rows -> 1024 independent one-warp blocks; warps slip
// freely (no cross-warp barriers) which hides the serial per-step latency.
// 4-deep register prefetch, manually unrolled x4 (compile-time slot indices).
#define GROUPS 16
#define ROWS   4
__global__ void scan_kernel()
{
    int idx = blockIdx.x;
    int g  = idx & (GROUPS - 1);
    int bh = idx >> 4;
    int b = bh >> 4, h = bh & 15;
    int tid = threadIdx.x;
    int row = tid >> 3;       // 0..3
    int c   = tid & 7;        // 0..7
    int c0  = c * 8;
    int j2  = tid * 2;

    __shared__ alignas(16) float sw[64], sr[64], sk[64], sb[64], snk[64], sv[ROWS];
    float S[8];
#pragma unroll
    for (int j = 0; j < 8; j++) S[j] = 0.f;

    size_t basebh = ((size_t)b * TT) * DD + h * HDIM;

    float2 Pw[4], Pr[4], Pk[4], Pb[4], Pn[4];
    float  Pv[4];
#pragma unroll
    for (int q = 0; q < 4; q++) {          // fully unrolled: static indices
        size_t pb = basebh + (size_t)q * DD;
        Pw[q] = *(const float2*)(g_w + pb + j2);
        Pr[q] = *(const float2*)(g_r + pb + j2);
        Pk[q] = *(const float2*)(g_k + pb + j2);
        Pb[q] = *(const float2*)(g_b + pb + j2);
        Pn[q] = *(const float2*)(g_kk + pb + j2);
        Pv[q] = (tid < ROWS) ? g_v[pb + g * ROWS + tid] : 0.f;
    }

    for (int t = 0; t < TT; t += 4) {
#pragma unroll
        for (int q = 0; q < 4; q++) {      // unrolled: Pw[q] etc. stay in regs
            int tq = t + q;
            *(float2*)&sw[j2]  = Pw[q];
            *(float2*)&sr[j2]  = Pr[q];
            *(float2*)&sk[j2]  = Pk[q];
            *(float2*)&sb[j2]  = Pb[q];
            *(float2*)&snk[j2] = Pn[q];
            if (tid < ROWS) sv[tid] = Pv[q];
            __syncwarp();

            if (tq + 4 < TT) {
                size_t pb = basebh + (size_t)(tq + 4) * DD;
                Pw[q] = *(const float2*)(g_w + pb + j2);
                Pr[q] = *(const float2*)(g_r + pb + j2);
                Pk[q] = *(const float2*)(g_k + pb + j2);
                Pb[q] = *(const float2*)(g_b + pb + j2);
                Pn[q] = *(const float2*)(g_kk + pb + j2);
                if (tid < ROWS) Pv[q] = g_v[pb + g * ROWS + tid];
            }

            float pa0 = 0.f, pa1 = 0.f;
#pragma unroll
            for (int j = 0; j < 4; j++)  pa0 = fmaf(S[j],     snk[c0 + j],     pa0);
#pragma unroll
            for (int j = 0; j < 4; j++)  pa1 = fmaf(S[j + 4], snk[c0 + j + 4], pa1);
            float pa = pa0 + pa1;
            pa += __shfl_xor_sync(0xffffffffu, pa, 1);
            pa += __shfl_xor_sync(0xffffffffu, pa, 2);
            pa += __shfl_xor_sync(0xffffffffu, pa, 4);

            float vr = sv[row];
            float po0 = 0.f, po1 = 0.f;
#pragma unroll
            for (int j = 0; j < 8; j++) {
                int kc = c0 + j;
                float ssv = fmaf(S[j], sw[kc], fmaf(pa, sb[kc], vr * sk[kc]));
                S[j] = ssv;
                if (j < 4) po0 = fmaf(ssv, sr[kc], po0);
                else       po1 = fmaf(ssv, sr[kc], po1);
            }
            float po = po0 + po1;
            po += __shfl_xor_sync(0xffffffffu, po, 1);
            po += __shfl_xor_sync(0xffffffffu, po, 2);
            po += __shfl_xor_sync(0xffffffffu, po, 4);
            if (c == 0) g_o[basebh + (size_t)tq * DD + g * ROWS + row] = po;
            __syncwarp();
        }
    }
}

// ---------------- post: GroupNorm(head) + corr + gate ---------------------
__global__ void post_kernel(const float* __restrict__ r_k,
                            const float* __restrict__ gnw,
                            const float* __restrict__ gnb)
{
    int hidx = blockIdx.x;
    int m = hidx >> 4, h = hidx & 15;
    int lane = threadIdx.x;
    size_t base = (size_t)m * DD + h * HDIM;
    int d0 = h * HDIM + lane, d1 = d0 + 32;

    float o0 = g_o[base + lane], o1 = g_o[base + lane + 32];
    float s = o0 + o1;
#pragma unroll
    for (int o = 16; o > 0; o >>= 1) s += __shfl_xor_sync(0xffffffffu, s, o);
    float mu = s * (1.f / 64.f);
    float e0 = o0 - mu, e1 = o1 - mu;
    float vs = e0 * e0 + e1 * e1;
#pragma unroll
    for (int o = 16; o > 0; o >>= 1) vs += __shfl_xor_sync(0xffffffffu, vs, o);
    float inv = rsqrtf(vs * (1.f / 64.f) + GN_EPS);

    float on0 = e0 * inv * gnw[d0] + gnb[d0];
    float on1 = e1 * inv * gnw[d1] + gnb[d1];

    float dot = g_r[base + lane]      * g_k[base + lane]      * r_k[d0]
              + g_r[base + lane + 32] * g_k[base + lane + 32] * r_k[d1];
#pragma unroll
    for (int o = 16; o > 0; o >>= 1) dot += __shfl_xor_sync(0xffffffffu, dot, o);

    g_y[base + lane]      = (on0 + dot * g_v[base + lane])      * g_g[base + lane];
    g_y[base + lane + 32] = (on1 + dot * g_v[base + lane + 32]) * g_g[base + lane + 32];
}

// ---------------------------------------------------------------------------
extern "C" void kernel_launch(void* const* d_in, const int* in_sizes, int n_in,
                              void* d_out, int out_size)
{
    const float* x     = (const float*)d_in[0];
    const float* mix_r = (const float*)d_in[1];
    const float* mix_w = (const float*)d_in[2];
    const float* mix_k = (const float*)d_in[3];
    const float* mix_v = (const float*)d_in[4];
    const float* mix_a = (const float*)d_in[5];
    const float* mix_g = (const float*)d_in[6];
    const float* k_k   = (const float*)d_in[7];
    const float* k_a   = (const float*)d_in[8];
    const float* r_k   = (const float*)d_in[9];
    const float* Wr    = (const float*)d_in[10];
    const float* Wk    = (const float*)d_in[11];
    const float* Wv    = (const float*)d_in[12];
    const float* Wo    = (const float*)d_in[13];
    const float* wA    = (const float*)d_in[14];
    const float* wB    = (const float*)d_in[15];
    const float* w_bias= (const float*)d_in[16];
    const float* aA    = (const float*)d_in[17];
    const float* aB    = (const float*)d_in[18];
    const float* a_bias= (const float*)d_in[19];
    const float* gA    = (const float*)d_in[20];
    const float* gB    = (const float*)d_in[21];
    const float* gnw   = (const float*)d_in[22];
    const float* gnb   = (const float*)d_in[23];
    float* out = (float*)d_out;

    float *pxr, *pxw, *pxk, *pxv, *pxa, *pxg;
    float *pr, *pw, *pk, *pv, *pa, *pg, *py, *puw, *pua, *pug;
    cudaGetSymbolAddress((void**)&pxr, g_xr);
    cudaGetSymbolAddress((void**)&pxw, g_xw);
    cudaGetSymbolAddress((void**)&pxk, g_xk);
    cudaGetSymbolAddress((void**)&pxv, g_xv);
    cudaGetSymbolAddress((void**)&pxa, g_xa);
    cudaGetSymbolAddress((void**)&pxg, g_xg);
    cudaGetSymbolAddress((void**)&pr,  g_r);
    cudaGetSymbolAddress((void**)&pw,  g_w);
    cudaGetSymbolAddress((void**)&pk,  g_k);
    cudaGetSymbolAddress((void**)&pv,  g_v);
    cudaGetSymbolAddress((void**)&pa,  g_a);
    cudaGetSymbolAddress((void**)&pg,  g_g);
    cudaGetSymbolAddress((void**)&py,  g_y);
    cudaGetSymbolAddress((void**)&puw, g_uw);
    cudaGetSymbolAddress((void**)&pua, g_ua);
    cudaGetSymbolAddress((void**)&pug, g_ug);

    // 1. token-shift mix -> 6 mixed inputs
    mix_kernel<<<MM * DD / 4 / 256, 256>>>(x, mix_r, mix_w, mix_k, mix_v, mix_a, mix_g);

    dim3 blk(256);
    dim3 grdBig(DD / 128, MM / 128);            // (8, 64) : N=1024
    dim3 grdUp64(1, MM / 128);                  // (1, 64) : N=64
    dim3 grdUp160((LOW_G + 63) / 64, MM / 128); // (3, 64) : N=160

    // 2. big projections (tf32 tensor cores)
    gemm_tf32<128,2,4,0><<<grdBig, blk>>>(pxr, Wr, pr, DD, DD, nullptr);
    gemm_tf32<128,2,4,0><<<grdBig, blk>>>(pxk, Wk, pk, DD, DD, nullptr);
    gemm_tf32<128,2,4,0><<<grdBig, blk>>>(pxv, Wv, pv, DD, DD, nullptr);

    // 3. w lora: tanh(xw@wA) @ wB + bias -> exp(DECAY_SCALE*sigmoid(.)) fused
    gemm_tf32<64,4,2,1><<<grdUp64, blk>>>(pxw, wA, puw, LOW_W, DD, nullptr);
    gemm_tf32<128,2,4,4><<<grdBig, blk>>>(puw, wB, pw, DD, LOW_W, w_bias);

    // 4. a lora: (xa@aA) @ aB + bias -> sigmoid
    gemm_tf32<64,4,2,0><<<grdUp64, blk>>>(pxa, aA, pua, LOW_A, DD, nullptr);
    gemm_tf32<128,2,4,2><<<grdBig, blk>>>(pua, aB, pa, DD, LOW_A, a_bias);

    // 5. g lora: sigmoid(xg@gA) @ gB
    gemm_tf32<64,4,2,2><<<grdUp160, blk>>>(pxg, gA, pug, LOW_G, DD, nullptr);
    gemm_tf32<128,2,4,0><<<grdBig, blk>>>(pug, gB, pg, DD, LOW_G, nullptr);

    // 6. kk normalize + b/nk precompute + k rescale
    prep_kernel<<<MM * HH, 32>>>(k_k, k_a);

    // 7. sequential generalized delta-rule scan (round-8 independent warps)
    scan_kernel<<<BB * HH * GROUPS, 32>>>();

    // 8. GroupNorm + correction + gate
    post_kernel<<<MM * HH, 32>>>(r_k, gnw, gnb);

    // 9. output projection
    gemm_tf32<128,2,4,0><<<grdBig, blk>>>(py, Wo, out, DD, DD, nullptr);
}